// round 16
// baseline (speedup 1.0000x reference)
#include <cuda_runtime.h>
#include <math.h>

#define NN 192
#define TT 20
#define DH 64
#define DE 32
#define DR 32
#define NB 96
#define NTH 512
#define RPB 2

// ---- device scratch (no allocations allowed) ----
__device__ float4 g_hB0p[NN*32], g_hB1p[NN*32];    // packed {h[l], h[l+32], B[l], B[l+32]}
__device__ float  g_b0v[NN], g_b1v[NN];
__device__ float  g_acc[4], g_v[3];
__device__ unsigned g_bar[1];                      // memset to 0 each launch
__device__ float g_wABT[2*2*64*64];                // [p][part][k][h] (h fastest)

struct __align__(16) Smem {
    float4 cst4[2*DR];            // {wrel_x, wrel_y, brel, war_k}
    float4 wg4[2*16*32];          // [p][kpair][lane]{w2k[h],w2k[h+32],w2k1[h],w2k1[h+32]}
    float2 wl2[96*128];           // LSTM weights [e][pair r]
    float2 r2[RPB][16*NN];        // [kpair][j] {r[2k],r[2k+1]}
    float2 msg2[RPB][8][32];
    float  wnei[2*64*64];         // [p][k][h]
    float  war[256];
    float  bcomb[256];
    float  bg[2*DH];
    float  bar2[2];
    float  wout[2*DH];
    float  bout[2];
    float  absv[RPB][2*NN];       // per-group copy (group decoupling + prefetch target)
    float  gates[RPB][256];
    float  xh[RPB][96];
    float  pos[RPB][NN];          // UNNORMALIZED e*nf
    float  hn[RPB][DH];
    float  A[RPB][DH];
    float  a[RPB];
    float  rr[RPB][24];
    float  v1[RPB][8];
    float  h[RPB][DH], c[RPB][DH], og[RPB][DH], ctmp[RPB][DH], msgf[RPB][DH];
    int    cnt[RPB];
    unsigned char seqb[RPB][NN];  // per-group copy
    unsigned char neib[RPB][NN];
    unsigned char actb[RPB][NN];
};

// group-local barrier: 256 threads of row-group g (named barrier g+1)
__device__ __forceinline__ void rbar(int g) {
    asm volatile("bar.sync %0, %1;" :: "r"(g + 1), "r"(256) : "memory");
}

// grid barrier: monotonic counter; release-red arrive + acquire poll
__device__ __forceinline__ void gbar(unsigned& target) {
    __syncthreads();
    if (threadIdx.x == 0) {
        target += NB;
        asm volatile("red.release.gpu.add.u32 [%0], 1;" :: "l"(g_bar) : "memory");
        unsigned v;
        do {
            asm volatile("ld.acquire.gpu.u32 %0, [%1];" : "=r"(v) : "l"(g_bar) : "memory");
        } while ((int)(v - target) < 0);
    }
    __syncthreads();
}

__device__ __forceinline__ float wsum(float v) {
#pragma unroll
    for (int o = 16; o; o >>= 1) v += __shfl_xor_sync(0xffffffffu, v, o);
    return v;
}
__device__ __forceinline__ float wmax(float v) {
#pragma unroll
    for (int o = 16; o; o >>= 1) v = fmaxf(v, __shfl_xor_sync(0xffffffffu, v, o));
    return v;
}
__device__ __forceinline__ float sigf(float x) { return 1.f/(1.f+__expf(-x)); }

__global__ void __launch_bounds__(NTH, 1)
fused_kernel(const float* __restrict__ abs_, const float* __restrict__ norm,
             const float* __restrict__ w_in, const float* __restrict__ b_in,
             const float* __restrict__ w_ih, const float* __restrict__ w_hh,
             const float* __restrict__ b_ih, const float* __restrict__ b_hh,
             const float* __restrict__ w_rel, const float* __restrict__ b_rel,
             const float* __restrict__ w_gate, const float* __restrict__ b_gate,
             const float* __restrict__ w_ar, const float* __restrict__ b_ar,
             const float* __restrict__ w_nei, const float* __restrict__ w_out,
             const float* __restrict__ b_out,
             const int* __restrict__ seq, const int* __restrict__ nei,
             float* __restrict__ out)
{
    extern __shared__ char smem_raw[];
    Smem& S = *reinterpret_cast<Smem*>(smem_raw);

    const int tid  = threadIdx.x;
    const int g    = tid >> 8;            // row group 0..1
    const int ltid = tid & 255;           // 0..255 within group
    const int lane = tid & 31;
    const int w8   = (tid >> 5) & 7;      // warp within group 0..7
    const int i    = blockIdx.x * RPB + g;
    const int gtid = blockIdx.x * NTH + tid;
    unsigned target = 0;

    // ---- one-time smem constant loads ----
    for (int idx = tid; idx < 96*128; idx += NTH) {
        int e = idx >> 7, p = idx & 127;
        int r0 = 2*p, r1 = 2*p + 1;
        float v0, v1;
        if (e < DE) { v0 = w_ih[r0*DE + e];        v1 = w_ih[r1*DE + e]; }
        else        { v0 = w_hh[r0*DH + (e - DE)]; v1 = w_hh[r1*DH + (e - DE)]; }
        S.wl2[idx] = make_float2(v0, v1);
    }
    for (int idx = tid; idx < 2*16*32; idx += NTH) {
        int p = idx >> 9, rem = idx & 511, kp = rem >> 5, l = rem & 31;
        const float* wp = w_gate + p*DH*160;
        S.wg4[idx] = make_float4(wp[l*160 + 2*kp],      wp[(l+32)*160 + 2*kp],
                                 wp[l*160 + 2*kp + 1],  wp[(l+32)*160 + 2*kp + 1]);
    }
    for (int idx = tid; idx < 2*64*64; idx += NTH) {
        int h = idx & 63, k = (idx >> 6) & 63, p = idx >> 12;
        S.wnei[idx] = w_nei[p*DH*DH + h*DH + k];
    }
    for (int idx = tid; idx < 2*DR; idx += NTH) {
        int p = idx >> 5, k = idx & 31;
        S.cst4[idx] = make_float4(w_rel[p*DR*2 + k*2 + 0], w_rel[p*DR*2 + k*2 + 1],
                                  b_rel[p*DR + k],          w_ar[p*160 + k]);
    }
    for (int idx = tid; idx < 256; idx += NTH) {
        int p = idx >> 7, part = (idx >> 6) & 1, k = idx & 63;
        S.war[idx] = w_ar[p*160 + 32 + part*64 + k];
    }
    if (tid < 256) S.bcomb[tid] = b_ih[tid] + b_hh[tid];
    if (tid < 2*DH) S.bg[tid] = b_gate[tid];
    if (tid < 128) S.wout[tid] = w_out[tid];
    if (tid < 2) { S.bar2[tid] = b_ar[tid]; S.bout[tid] = b_out[tid]; }
    if (ltid < DH) { S.h[g][ltid] = 0.f; S.c[g][ltid] = 0.f; }
    if (ltid == 0) S.cnt[g] = 0;

    // ---- one-time global transposes + zero init ----
    for (int idx = gtid; idx < 2*2*64*64; idx += NB*NTH) {
        int h = idx & 63, k = (idx >> 6) & 63, part = (idx >> 12) & 1, p = idx >> 13;
        g_wABT[idx] = w_gate[p*DH*160 + h*160 + 32 + part*64 + k];
    }
    if (gtid < NN*2) out[(TT-1)*NN*2 + gtid] = 0.f;
    if (blockIdx.x == 0 && tid < 4) g_acc[tid] = 0.f;
    if (blockIdx.x == 0 && tid < 3) g_v[tid] = 0.f;
    gbar(target);

    for (int t = 0; t < TT-1; t++) {
        //================ Phase A: LSTM + pre0 (inputs prefetched in prior C) ====
        if (t == 0) {
            S.absv[g][ltid] = abs_[ltid];
            if (ltid < 2*NN - 256) S.absv[g][256 + ltid] = abs_[256 + ltid];
            if (ltid < NN) {
                S.seqb[g][ltid] = (unsigned char)(seq[ltid] > 0);
                S.neib[g][ltid] = (unsigned char)(nei[(size_t)i*NN + ltid] > 0);
            }
            if (ltid < DE) {
                float n0 = norm[i*2 + 0];
                float n1 = norm[i*2 + 1];
                S.xh[g][ltid] = fmaxf(n0*w_in[ltid*2+0] + n1*w_in[ltid*2+1] + b_in[ltid], 0.f);
            }
        }
        if (ltid >= 64 && ltid < 128) S.xh[g][32 + (ltid - 64)] = S.h[g][ltid - 64];
        rbar(g);
        const int mi = S.seqb[g][i];
        if (ltid < 128) {   // LSTM gates: 2 per thread, 4 accumulator chains
            const float2* bc2 = (const float2*)S.bcomb;
            float2 A0 = bc2[ltid];
            float2 A1 = make_float2(0.f, 0.f);
            float2 A2 = make_float2(0.f, 0.f);
            float2 A3 = make_float2(0.f, 0.f);
#pragma unroll
            for (int e = 0; e < 96; e += 4) {
                float x0 = S.xh[g][e],   x1 = S.xh[g][e+1];
                float x2 = S.xh[g][e+2], x3 = S.xh[g][e+3];
                float2 w0 = S.wl2[e*128 + ltid];
                float2 w1 = S.wl2[(e+1)*128 + ltid];
                float2 w2 = S.wl2[(e+2)*128 + ltid];
                float2 w3 = S.wl2[(e+3)*128 + ltid];
                A0.x += x0*w0.x; A0.y += x0*w0.y;
                A1.x += x1*w1.x; A1.y += x1*w1.y;
                A2.x += x2*w2.x; A2.y += x2*w2.y;
                A3.x += x3*w3.x; A3.y += x3*w3.y;
            }
            ((float2*)S.gates[g])[ltid] =
                make_float2((A0.x + A1.x) + (A2.x + A3.x),
                            (A0.y + A1.y) + (A2.y + A3.y));
        }
        rbar(g);
        if (ltid < DH) {
            int h = ltid;
            float ig = sigf(S.gates[g][h]);
            float fg = sigf(S.gates[g][64 + h]);
            float gg = tanhf(S.gates[g][128 + h]);
            float og = sigf(S.gates[g][192 + h]);
            float c1 = fg*S.c[g][h] + ig*gg;
            float h1 = og*tanhf(c1);
            S.ctmp[g][h] = c1;
            S.og[g][h] = og;
            S.hn[g][h] = h1;
        }
        rbar(g);
        if (mi) {   // merged pre0: warp0 = full A, warp1 = full B + shuffle transpose
            if (w8 == 0) {
                const float2* wp = (const float2*)(g_wABT + 0*4096);
                float sx = 0.f, sy = 0.f, tx = 0.f, ty = 0.f;
#pragma unroll
                for (int k = 0; k < 64; k += 2) {
                    float h0 = S.hn[g][k], h1 = S.hn[g][k+1];
                    float2 w0 = wp[k*32 + lane], w1 = wp[(k+1)*32 + lane];
                    sx += h0*w0.x; sy += h0*w0.y;
                    tx += h1*w1.x; ty += h1*w1.y;
                }
                ((float2*)S.A[g])[lane] = make_float2(sx + tx, sy + ty);
            } else if (w8 == 1) {
                const float2* wp = (const float2*)(g_wABT + 1*4096);
                float sx = 0.f, sy = 0.f, tx = 0.f, ty = 0.f;
#pragma unroll
                for (int k = 0; k < 64; k += 2) {
                    float h0 = S.hn[g][k], h1 = S.hn[g][k+1];
                    float2 w0 = wp[k*32 + lane], w1 = wp[(k+1)*32 + lane];
                    sx += h0*w0.x; sy += h0*w0.y;
                    tx += h1*w1.x; ty += h1*w1.y;
                }
                float bx = sx + tx, by = sy + ty;   // {B[2l], B[2l+1]}
                float e0 = __shfl_sync(0xffffffffu, bx, lane >> 1);
                float e1 = __shfl_sync(0xffffffffu, by, lane >> 1);
                float Bl = (lane & 1) ? e1 : e0;
                float e2 = __shfl_sync(0xffffffffu, bx, 16 + (lane >> 1));
                float e3 = __shfl_sync(0xffffffffu, by, 16 + (lane >> 1));
                float Bh = (lane & 1) ? e3 : e2;
                g_hB0p[i*32 + lane] = make_float4(S.hn[g][lane], S.hn[g][32 + lane], Bl, Bh);
            } else if (w8 == 4) {
                float pa = S.hn[g][lane]*S.war[lane] + S.hn[g][32+lane]*S.war[32+lane];
                pa = wsum(pa);
                if (lane == 0) S.a[g] = pa;
            } else if (w8 == 5) {
                float pb = S.hn[g][lane]*S.war[64+lane] + S.hn[g][32+lane]*S.war[96+lane];
                pb = wsum(pb);
                if (lane == 0) g_b0v[i] = pb;
            }
        }
        gbar(target);

        //================ Phases B (stage0) and C (stage1) ================
#pragma unroll 1
        for (int STAGE = 0; STAGE < 2; STAGE++) {
            if (STAGE == 1 && blockIdx.x == 0 && tid == 0) {
                const float eps = 1e-6f;
                g_v[0] += g_acc[0] / (g_acc[1]*(float)DH + eps);
                g_v[1] += g_acc[2] / (g_acc[3] + eps);
                g_v[2] += g_acc[1] / (float)NN;
                g_acc[0] = g_acc[1] = g_acc[2] = g_acc[3] = 0.f;
            }
            const float4* hBp = STAGE ? g_hB1p : g_hB0p;
            const float*  gbv = STAGE ? g_b1v : g_b0v;
            const float   barv = S.bar2[STAGE];
            const float   aI   = S.a[g];
            const float   ax = S.absv[g][2*i], ay = S.absv[g][2*i+1];
            const float4* cst = S.cst4 + STAGE*DR;

            // ---- score stage: scores + r2 cache + pos(e*nf) + compaction + reductions
            float nf1 = 0.f, sc1 = -1e30f;
            const int j1 = ltid;
            if (mi && j1 < NN) {
                nf1 = (S.neib[g][j1] && S.seqb[g][j1]) ? 1.f : 0.f;
                float bj = __ldcg(&gbv[j1]);
                float cx = ax - S.absv[g][2*j1], cy = ay - S.absv[g][2*j1+1];
                float scE = 0.f, scO = 0.f;
#pragma unroll
                for (int kp = 0; kp < 16; kp++) {
                    float4 c0 = cst[2*kp], c1 = cst[2*kp+1];
                    float r0 = fmaxf(fmaf(cx, c0.x, fmaf(cy, c0.y, c0.z)), 0.f);
                    float r1 = fmaxf(fmaf(cx, c1.x, fmaf(cy, c1.y, c1.z)), 0.f);
                    S.r2[g][kp*NN + j1] = make_float2(r0, r1);
                    scE += r0 * c0.w;
                    scO += r1 * c1.w;
                }
                float sc = scE + scO + aI + bj + barv;
                sc1 = (nf1 > 0.f) ? sc : -1e9f;
            }
            float e1 = __expf(sc1);     // masked -> 0
            if (j1 < NN) S.pos[g][j1] = e1 * nf1;   // UNNORMALIZED
            {   // compaction (needs only nf1; cnt was reset last stage under barrier)
                unsigned b1 = __ballot_sync(0xffffffffu, nf1 > 0.f);
                int base = 0;
                if (lane == 0 && b1) base = atomicAdd(&S.cnt[g], __popc(b1));
                base = __shfl_sync(0xffffffffu, base, 0);
                if (nf1 > 0.f)
                    S.actb[g][base + __popc(b1 & ((1u << lane) - 1u))] = (unsigned char)j1;
            }
            {   // merged reduction: sum(e), max(e*nf), sum(nf)
                float se = wsum(e1), mn = wmax(e1*nf1), sn = wsum(nf1);
                if (lane == 0) { S.rr[g][w8] = se; S.rr[g][8+w8] = mn; S.rr[g][16+w8] = sn; }
            }
            rbar(g);
            float ssum = 0.f, mpos = 0.f, neiRow = 0.f;
#pragma unroll
            for (int w = 0; w < 8; w++) {
                ssum += S.rr[g][w];
                mpos = fmaxf(mpos, S.rr[g][8+w]);
                neiRow += S.rr[g][16+w];
            }
            const float inv = (ssum > 0.f) ? 1.f/ssum : 0.f;
            const float maxposRow = mpos * inv;
            // ---- input prefetch for t+1 (stage1 only; absv/seqb/neib/xh dead now) ----
            if (STAGE == 1 && t + 1 < TT-1) {
                int t2 = t + 1;
                S.absv[g][ltid] = abs_[t2*2*NN + ltid];
                if (ltid < 2*NN - 256) S.absv[g][256 + ltid] = abs_[t2*2*NN + 256 + ltid];
                if (ltid < NN) {
                    S.seqb[g][ltid] = (unsigned char)(seq[t2*NN + ltid] > 0);
                    S.neib[g][ltid] =
                        (unsigned char)(nei[(size_t)t2*NN*NN + (size_t)i*NN + ltid] > 0);
                }
                if (ltid < DE) {
                    float n0 = norm[(t2*NN + i)*2 + 0];
                    float n1 = norm[(t2*NN + i)*2 + 1];
                    S.xh[g][ltid] = fmaxf(n0*w_in[ltid*2+0] + n1*w_in[ltid*2+1] + b_in[ltid], 0.f);
                }
            }
            // ---- gate + message loop: 4 neighbors/iter, interleaved slots ----
            const float Ai0 = S.A[g][lane]      + S.bg[STAGE*DH + lane];
            const float Ai1 = S.A[g][32 + lane] + S.bg[STAGE*DH + 32 + lane];
            const float4* wg4 = S.wg4 + STAGE*16*32;
            const float2* rS2 = S.r2[g];
            float msg0 = 0.f, msg1 = 0.f, v1p = 0.f;
            const int cnt = S.cnt[g];
            for (int base = w8; base < cnt; base += 32) {
                int aa = base, ab = base + 8, ac = base + 16, ad = base + 24;
                bool vb = ab < cnt, vc = ac < cnt, vd = ad < cnt;
                int ja = S.actb[g][aa];
                int jb = vb ? S.actb[g][ab] : ja;
                int jc = vc ? S.actb[g][ac] : ja;
                int jd = vd ? S.actb[g][ad] : ja;
                float4 HA = __ldcg(&hBp[ja*32 + lane]);   // 4 loads in flight,
                float4 HB = __ldcg(&hBp[jb*32 + lane]);   // consumed after k-loop
                float4 HC = __ldcg(&hBp[jc*32 + lane]);
                float4 HD = __ldcg(&hBp[jd*32 + lane]);
                float a0 = Ai0, a1 = Ai1, b0 = Ai0, b1 = Ai1;
                float c0 = Ai0, c1 = Ai1, d0 = Ai0, d1 = Ai1;
#pragma unroll
                for (int kp = 0; kp < 16; kp++) {
                    float4 w4 = wg4[kp*32 + lane];
                    float2 ra = rS2[kp*NN + ja];
                    float2 rb = rS2[kp*NN + jb];
                    float2 rc = rS2[kp*NN + jc];
                    float2 rd = rS2[kp*NN + jd];
                    a0 += ra.x*w4.x + ra.y*w4.z;  a1 += ra.x*w4.y + ra.y*w4.w;
                    b0 += rb.x*w4.x + rb.y*w4.z;  b1 += rb.x*w4.y + rb.y*w4.w;
                    c0 += rc.x*w4.x + rc.y*w4.z;  c1 += rc.x*w4.y + rc.y*w4.w;
                    d0 += rd.x*w4.x + rd.y*w4.z;  d1 += rd.x*w4.y + rd.y*w4.w;
                }
                a0 += HA.z; a1 += HA.w; b0 += HB.z; b1 += HB.w;
                c0 += HC.z; c1 += HC.w; d0 += HD.z; d1 += HD.w;
                float ga0 = sigf(a0), ga1 = sigf(a1);
                float gb0 = sigf(b0), gb1 = sigf(b1);
                float gc0 = sigf(c0), gc1 = sigf(c1);
                float gd0 = sigf(d0), gd1 = sigf(d1);
                float pa = S.pos[g][ja] * inv;
                float pb = vb ? S.pos[g][jb] * inv : 0.f;
                float pc = vc ? S.pos[g][jc] * inv : 0.f;
                float pd = vd ? S.pos[g][jd] * inv : 0.f;
                msg0 += (pa*ga0*HA.x + pb*gb0*HB.x) + (pc*gc0*HC.x + pd*gd0*HD.x);
                msg1 += (pa*ga1*HA.y + pb*gb1*HB.y) + (pc*gc1*HC.y + pd*gd1*HD.y);
                v1p += ga0 + ga1;
                if (vb) v1p += gb0 + gb1;
                if (vc) v1p += gc0 + gc1;
                if (vd) v1p += gd0 + gd1;
            }
            S.msg2[g][w8][lane] = make_float2(msg0, msg1);
            if (STAGE == 0) {
                v1p = wsum(v1p);
                if (lane == 0) S.v1[g][w8] = v1p;
            }
            rbar(g);
            if (ltid < DH) {
                int h = ltid;
                float v = 0.f;
#pragma unroll
                for (int w = 0; w < 8; w++)
                    v += (h < 32) ? S.msg2[g][w][h].x : S.msg2[g][w][h-32].y;
                S.msgf[g][h] = v;
            }
            if (ltid == 128) S.cnt[g] = 0;   // safe: all gate-loop reads done (rbar above)
            rbar(g);
            // ---- merged cn GEMV + hn update (64 threads, 4 accumulators) ----
            if (ltid < DH) {
                int h = ltid;
                float cn = S.ctmp[g][h];
                float hn = S.hn[g][h];
                if (cnt) {
                    const float* wn = S.wnei + STAGE*4096;
                    float q0 = 0.f, q1 = 0.f, q2 = 0.f, q3 = 0.f;
#pragma unroll
                    for (int k = 0; k < 64; k += 4) {
                        q0 += S.msgf[g][k]   * wn[k*64 + h];
                        q1 += S.msgf[g][k+1] * wn[(k+1)*64 + h];
                        q2 += S.msgf[g][k+2] * wn[(k+2)*64 + h];
                        q3 += S.msgf[g][k+3] * wn[(k+3)*64 + h];
                    }
                    cn += (q0 + q1) + (q2 + q3);
                    hn = S.og[g][h]*tanhf(cn);
                }
                S.ctmp[g][h] = cn;
                S.hn[g][h] = hn;
                if (STAGE == 1 && mi) { S.h[g][h] = hn; S.c[g][h] = cn; }
            }
            rbar(g);
            if (STAGE == 0) {
                if (mi) {   // merged pre1 (full-k per warp) + stats
                    if (w8 == 0) {
                        const float2* wp = (const float2*)(g_wABT + 2*4096);
                        float sx = 0.f, sy = 0.f, tx = 0.f, ty = 0.f;
#pragma unroll
                        for (int k = 0; k < 64; k += 2) {
                            float h0 = S.hn[g][k], h1 = S.hn[g][k+1];
                            float2 w0 = wp[k*32 + lane], w1 = wp[(k+1)*32 + lane];
                            sx += h0*w0.x; sy += h0*w0.y;
                            tx += h1*w1.x; ty += h1*w1.y;
                        }
                        ((float2*)S.A[g])[lane] = make_float2(sx + tx, sy + ty);
                    } else if (w8 == 1) {
                        const float2* wp = (const float2*)(g_wABT + 3*4096);
                        float sx = 0.f, sy = 0.f, tx = 0.f, ty = 0.f;
#pragma unroll
                        for (int k = 0; k < 64; k += 2) {
                            float h0 = S.hn[g][k], h1 = S.hn[g][k+1];
                            float2 w0 = wp[k*32 + lane], w1 = wp[(k+1)*32 + lane];
                            sx += h0*w0.x; sy += h0*w0.y;
                            tx += h1*w1.x; ty += h1*w1.y;
                        }
                        float bx = sx + tx, by = sy + ty;
                        float e0 = __shfl_sync(0xffffffffu, bx, lane >> 1);
                        float e1b = __shfl_sync(0xffffffffu, by, lane >> 1);
                        float Bl = (lane & 1) ? e1b : e0;
                        float e2 = __shfl_sync(0xffffffffu, bx, 16 + (lane >> 1));
                        float e3 = __shfl_sync(0xffffffffu, by, 16 + (lane >> 1));
                        float Bh = (lane & 1) ? e3 : e2;
                        g_hB1p[i*32 + lane] = make_float4(S.hn[g][lane], S.hn[g][32 + lane], Bl, Bh);
                    } else if (w8 == 4) {
                        float pa = S.hn[g][lane]*S.war[128+lane] + S.hn[g][32+lane]*S.war[160+lane];
                        pa = wsum(pa);
                        if (lane == 0) S.a[g] = pa;
                    } else if (w8 == 5) {
                        float pb = S.hn[g][lane]*S.war[192+lane] + S.hn[g][32+lane]*S.war[224+lane];
                        pb = wsum(pb);
                        if (lane == 0) g_b1v[i] = pb;
                    } else if (w8 == 6 && lane == 0) {
                        float gateSum = 0.f;
#pragma unroll
                        for (int w = 0; w < 8; w++) gateSum += S.v1[g][w];
                        atomicAdd(&g_acc[0], gateSum);
                        atomicAdd(&g_acc[1], neiRow);
                        atomicAdd(&g_acc[2], maxposRow);
                        atomicAdd(&g_acc[3], neiRow > 0.f ? 1.f : 0.f);
                    }
                }
                gbar(target);
            } else {
                // outputs via 2 warp reductions
                if (w8 == 6) {
                    float o = S.hn[g][lane]*S.wout[lane] + S.hn[g][32+lane]*S.wout[32+lane];
                    o = wsum(o);
                    if (lane == 0) out[(t*NN + i)*2 + 0] = mi ? (o + S.bout[0]) : 0.f;
                } else if (w8 == 7) {
                    float o = S.hn[g][lane]*S.wout[64+lane] + S.hn[g][32+lane]*S.wout[96+lane];
                    o = wsum(o);
                    if (lane == 0) out[(t*NN + i)*2 + 1] = mi ? (o + S.bout[1]) : 0.f;
                }
            }
        }
        // no grid barrier between C and next A; groups are data-decoupled
    }

    // final writeback
    const int OFF = TT*NN*2;
    if (ltid < DH) {
        out[OFF + i*DH + ltid]         = S.h[g][ltid];
        out[OFF + NN*DH + i*DH + ltid] = S.c[g][ltid];
    }
    if (blockIdx.x == 0 && tid < 3) out[OFF + 2*NN*DH + tid] = g_v[tid] / (float)TT;
}

extern "C" void kernel_launch(void* const* d_in, const int* in_sizes, int n_in,
                              void* d_out, int out_size) {
    const float* abs_   = (const float*)d_in[0];
    const float* norm   = (const float*)d_in[1];
    const float* w_in   = (const float*)d_in[3];
    const float* b_in   = (const float*)d_in[4];
    const float* w_ih   = (const float*)d_in[5];
    const float* w_hh   = (const float*)d_in[6];
    const float* b_ih   = (const float*)d_in[7];
    const float* b_hh   = (const float*)d_in[8];
    const float* w_rel  = (const float*)d_in[9];
    const float* b_rel  = (const float*)d_in[10];
    const float* w_gate = (const float*)d_in[11];
    const float* b_gate = (const float*)d_in[12];
    const float* w_ar   = (const float*)d_in[13];
    const float* b_ar   = (const float*)d_in[14];
    const float* w_nei  = (const float*)d_in[15];
    const float* w_out  = (const float*)d_in[16];
    const float* b_out  = (const float*)d_in[17];
    const int*   seq    = (const int*)d_in[18];
    const int*   nei    = (const int*)d_in[19];
    float* out = (float*)d_out;

    cudaFuncSetAttribute(fused_kernel, cudaFuncAttributeMaxDynamicSharedMemorySize,
                         (int)sizeof(Smem));

    void* barptr = nullptr;
    cudaGetSymbolAddress(&barptr, g_bar);
    cudaMemsetAsync(barptr, 0, sizeof(unsigned), 0);

    fused_kernel<<<NB, NTH, sizeof(Smem)>>>(abs_, norm, w_in, b_in, w_ih, w_hh, b_ih, b_hh,
                                            w_rel, b_rel, w_gate, b_gate, w_ar, b_ar,
                                            w_nei, w_out, b_out, seq, nei, out);
}

// round 17
// speedup vs baseline: 1.0534x; 1.0534x over previous
#include <cuda_runtime.h>
#include <math.h>

#define NN 192
#define TT 20
#define DH 64
#define DE 32
#define DR 32
#define NB 96
#define NTH 512
#define RPB 2

// ---- device scratch (no allocations allowed) ----
__device__ float4 g_hB0p[NN*32], g_hB1p[NN*32];    // packed {h[l], h[l+32], B[l], B[l+32]}
__device__ float  g_b0v[NN], g_b1v[NN];
__device__ float  g_acc[4], g_v[3];
__device__ unsigned g_bar[1];                      // memset to 0 each launch
__device__ float g_wABT[2*2*64*64];                // [p][part][k][h] (h fastest)

struct __align__(16) Smem {
    float4 cst4[2*DR];            // {wrel_x, wrel_y, brel, war_k}
    float4 wg4[2*16*32];          // [p][kpair][lane]{w2k[h],w2k[h+32],w2k1[h],w2k1[h+32]}
    float2 wl2[96*128];           // LSTM weights [e][pair r]
    float2 r2[RPB][16*NN];        // [kpair][j] {r[2k],r[2k+1]}
    float2 msg2[RPB][8][32];
    float  wnei[2*64*64];         // [p][k][h]
    float  war[256];
    float  bcomb[256];
    float  bg[2*DH];
    float  bar2[2];
    float  wout[2*DH];
    float  bout[2];
    float  absv[RPB][2*NN];       // per-group copy (group decoupling + prefetch target)
    float  gates[RPB][256];
    float  xh[RPB][96];
    float  pos[RPB][NN];          // UNNORMALIZED e*nf
    float  hn[RPB][DH];
    float  A[RPB][DH];
    float  a[RPB];
    float  rr[RPB][24];
    float  v1[RPB][8];
    float  h[RPB][DH], c[RPB][DH], og[RPB][DH], ctmp[RPB][DH], msgf[RPB][DH];
    int    cnt[RPB];
    unsigned char seqb[RPB][NN];  // per-group copy
    unsigned char neib[RPB][NN];
    unsigned char actb[RPB][NN];
};

// group-local barrier: 256 threads of row-group g (named barrier g+1)
__device__ __forceinline__ void rbar(int g) {
    asm volatile("bar.sync %0, %1;" :: "r"(g + 1), "r"(256) : "memory");
}

// grid barrier: monotonic counter; release-red arrive + acquire poll
__device__ __forceinline__ void gbar(unsigned& target) {
    __syncthreads();
    if (threadIdx.x == 0) {
        target += NB;
        asm volatile("red.release.gpu.add.u32 [%0], 1;" :: "l"(g_bar) : "memory");
        unsigned v;
        do {
            asm volatile("ld.acquire.gpu.u32 %0, [%1];" : "=r"(v) : "l"(g_bar) : "memory");
        } while ((int)(v - target) < 0);
    }
    __syncthreads();
}

__device__ __forceinline__ float wsum(float v) {
#pragma unroll
    for (int o = 16; o; o >>= 1) v += __shfl_xor_sync(0xffffffffu, v, o);
    return v;
}
__device__ __forceinline__ float wmax(float v) {
#pragma unroll
    for (int o = 16; o; o >>= 1) v = fmaxf(v, __shfl_xor_sync(0xffffffffu, v, o));
    return v;
}
__device__ __forceinline__ float sigf(float x) { return 1.f/(1.f+__expf(-x)); }

__global__ void __launch_bounds__(NTH, 1)
fused_kernel(const float* __restrict__ abs_, const float* __restrict__ norm,
             const float* __restrict__ w_in, const float* __restrict__ b_in,
             const float* __restrict__ w_ih, const float* __restrict__ w_hh,
             const float* __restrict__ b_ih, const float* __restrict__ b_hh,
             const float* __restrict__ w_rel, const float* __restrict__ b_rel,
             const float* __restrict__ w_gate, const float* __restrict__ b_gate,
             const float* __restrict__ w_ar, const float* __restrict__ b_ar,
             const float* __restrict__ w_nei, const float* __restrict__ w_out,
             const float* __restrict__ b_out,
             const int* __restrict__ seq, const int* __restrict__ nei,
             float* __restrict__ out)
{
    extern __shared__ char smem_raw[];
    Smem& S = *reinterpret_cast<Smem*>(smem_raw);

    const int tid  = threadIdx.x;
    const int g    = tid >> 8;            // row group 0..1
    const int ltid = tid & 255;           // 0..255 within group
    const int lane = tid & 31;
    const int w8   = (tid >> 5) & 7;      // warp within group 0..7
    const int i    = blockIdx.x * RPB + g;
    const int gtid = blockIdx.x * NTH + tid;
    unsigned target = 0;

    // ---- one-time smem constant loads ----
    for (int idx = tid; idx < 96*128; idx += NTH) {
        int e = idx >> 7, p = idx & 127;
        int r0 = 2*p, r1 = 2*p + 1;
        float v0, v1;
        if (e < DE) { v0 = w_ih[r0*DE + e];        v1 = w_ih[r1*DE + e]; }
        else        { v0 = w_hh[r0*DH + (e - DE)]; v1 = w_hh[r1*DH + (e - DE)]; }
        S.wl2[idx] = make_float2(v0, v1);
    }
    for (int idx = tid; idx < 2*16*32; idx += NTH) {
        int p = idx >> 9, rem = idx & 511, kp = rem >> 5, l = rem & 31;
        const float* wp = w_gate + p*DH*160;
        S.wg4[idx] = make_float4(wp[l*160 + 2*kp],      wp[(l+32)*160 + 2*kp],
                                 wp[l*160 + 2*kp + 1],  wp[(l+32)*160 + 2*kp + 1]);
    }
    for (int idx = tid; idx < 2*64*64; idx += NTH) {
        int h = idx & 63, k = (idx >> 6) & 63, p = idx >> 12;
        S.wnei[idx] = w_nei[p*DH*DH + h*DH + k];
    }
    for (int idx = tid; idx < 2*DR; idx += NTH) {
        int p = idx >> 5, k = idx & 31;
        S.cst4[idx] = make_float4(w_rel[p*DR*2 + k*2 + 0], w_rel[p*DR*2 + k*2 + 1],
                                  b_rel[p*DR + k],          w_ar[p*160 + k]);
    }
    for (int idx = tid; idx < 256; idx += NTH) {
        int p = idx >> 7, part = (idx >> 6) & 1, k = idx & 63;
        S.war[idx] = w_ar[p*160 + 32 + part*64 + k];
    }
    if (tid < 256) S.bcomb[tid] = b_ih[tid] + b_hh[tid];
    if (tid < 2*DH) S.bg[tid] = b_gate[tid];
    if (tid < 128) S.wout[tid] = w_out[tid];
    if (tid < 2) { S.bar2[tid] = b_ar[tid]; S.bout[tid] = b_out[tid]; }
    if (ltid < DH) { S.h[g][ltid] = 0.f; S.c[g][ltid] = 0.f; }
    if (ltid == 0) S.cnt[g] = 0;

    // ---- one-time global transposes + zero init ----
    for (int idx = gtid; idx < 2*2*64*64; idx += NB*NTH) {
        int h = idx & 63, k = (idx >> 6) & 63, part = (idx >> 12) & 1, p = idx >> 13;
        g_wABT[idx] = w_gate[p*DH*160 + h*160 + 32 + part*64 + k];
    }
    if (gtid < NN*2) out[(TT-1)*NN*2 + gtid] = 0.f;
    if (blockIdx.x == 0 && tid < 4) g_acc[tid] = 0.f;
    if (blockIdx.x == 0 && tid < 3) g_v[tid] = 0.f;
    gbar(target);

    for (int t = 0; t < TT-1; t++) {
        //================ Phase A: LSTM + pre0 (inputs prefetched in prior C) ====
        if (t == 0) {
            S.absv[g][ltid] = abs_[ltid];
            if (ltid < 2*NN - 256) S.absv[g][256 + ltid] = abs_[256 + ltid];
            if (ltid < NN) {
                S.seqb[g][ltid] = (unsigned char)(seq[ltid] > 0);
                S.neib[g][ltid] = (unsigned char)(nei[(size_t)i*NN + ltid] > 0);
            }
            if (ltid < DE) {
                float n0 = norm[i*2 + 0];
                float n1 = norm[i*2 + 1];
                S.xh[g][ltid] = fmaxf(n0*w_in[ltid*2+0] + n1*w_in[ltid*2+1] + b_in[ltid], 0.f);
            }
        }
        if (ltid >= 64 && ltid < 128) S.xh[g][32 + (ltid - 64)] = S.h[g][ltid - 64];
        rbar(g);
        const int mi = S.seqb[g][i];
        if (ltid < 128) {   // LSTM gates: 2 per thread, 4 accumulator chains
            const float2* bc2 = (const float2*)S.bcomb;
            float2 A0 = bc2[ltid];
            float2 A1 = make_float2(0.f, 0.f);
            float2 A2 = make_float2(0.f, 0.f);
            float2 A3 = make_float2(0.f, 0.f);
#pragma unroll
            for (int e = 0; e < 96; e += 4) {
                float x0 = S.xh[g][e],   x1 = S.xh[g][e+1];
                float x2 = S.xh[g][e+2], x3 = S.xh[g][e+3];
                float2 w0 = S.wl2[e*128 + ltid];
                float2 w1 = S.wl2[(e+1)*128 + ltid];
                float2 w2 = S.wl2[(e+2)*128 + ltid];
                float2 w3 = S.wl2[(e+3)*128 + ltid];
                A0.x += x0*w0.x; A0.y += x0*w0.y;
                A1.x += x1*w1.x; A1.y += x1*w1.y;
                A2.x += x2*w2.x; A2.y += x2*w2.y;
                A3.x += x3*w3.x; A3.y += x3*w3.y;
            }
            ((float2*)S.gates[g])[ltid] =
                make_float2((A0.x + A1.x) + (A2.x + A3.x),
                            (A0.y + A1.y) + (A2.y + A3.y));
        }
        rbar(g);
        if (ltid < DH) {
            int h = ltid;
            float ig = sigf(S.gates[g][h]);
            float fg = sigf(S.gates[g][64 + h]);
            float gg = tanhf(S.gates[g][128 + h]);
            float og = sigf(S.gates[g][192 + h]);
            float c1 = fg*S.c[g][h] + ig*gg;
            float h1 = og*tanhf(c1);
            S.ctmp[g][h] = c1;
            S.og[g][h] = og;
            S.hn[g][h] = h1;
        }
        rbar(g);
        if (mi) {   // merged pre0: warp0 = full A, warp1 = full B + shuffle transpose
            if (w8 == 0) {
                const float2* wp = (const float2*)(g_wABT + 0*4096);
                float sx = 0.f, sy = 0.f, tx = 0.f, ty = 0.f;
#pragma unroll
                for (int k = 0; k < 64; k += 2) {
                    float h0 = S.hn[g][k], h1 = S.hn[g][k+1];
                    float2 w0 = wp[k*32 + lane], w1 = wp[(k+1)*32 + lane];
                    sx += h0*w0.x; sy += h0*w0.y;
                    tx += h1*w1.x; ty += h1*w1.y;
                }
                ((float2*)S.A[g])[lane] = make_float2(sx + tx, sy + ty);
            } else if (w8 == 1) {
                const float2* wp = (const float2*)(g_wABT + 1*4096);
                float sx = 0.f, sy = 0.f, tx = 0.f, ty = 0.f;
#pragma unroll
                for (int k = 0; k < 64; k += 2) {
                    float h0 = S.hn[g][k], h1 = S.hn[g][k+1];
                    float2 w0 = wp[k*32 + lane], w1 = wp[(k+1)*32 + lane];
                    sx += h0*w0.x; sy += h0*w0.y;
                    tx += h1*w1.x; ty += h1*w1.y;
                }
                float bx = sx + tx, by = sy + ty;   // {B[2l], B[2l+1]}
                float e0 = __shfl_sync(0xffffffffu, bx, lane >> 1);
                float e1 = __shfl_sync(0xffffffffu, by, lane >> 1);
                float Bl = (lane & 1) ? e1 : e0;
                float e2 = __shfl_sync(0xffffffffu, bx, 16 + (lane >> 1));
                float e3 = __shfl_sync(0xffffffffu, by, 16 + (lane >> 1));
                float Bh = (lane & 1) ? e3 : e2;
                g_hB0p[i*32 + lane] = make_float4(S.hn[g][lane], S.hn[g][32 + lane], Bl, Bh);
            } else if (w8 == 4) {
                float pa = S.hn[g][lane]*S.war[lane] + S.hn[g][32+lane]*S.war[32+lane];
                pa = wsum(pa);
                if (lane == 0) S.a[g] = pa;
            } else if (w8 == 5) {
                float pb = S.hn[g][lane]*S.war[64+lane] + S.hn[g][32+lane]*S.war[96+lane];
                pb = wsum(pb);
                if (lane == 0) g_b0v[i] = pb;
            }
        }
        gbar(target);

        //================ Phases B (stage0) and C (stage1) ================
#pragma unroll 1
        for (int STAGE = 0; STAGE < 2; STAGE++) {
            if (STAGE == 1 && blockIdx.x == 0 && tid == 0) {
                const float eps = 1e-6f;
                g_v[0] += g_acc[0] / (g_acc[1]*(float)DH + eps);
                g_v[1] += g_acc[2] / (g_acc[3] + eps);
                g_v[2] += g_acc[1] / (float)NN;
                g_acc[0] = g_acc[1] = g_acc[2] = g_acc[3] = 0.f;
            }
            const float4* hBp = STAGE ? g_hB1p : g_hB0p;
            const float*  gbv = STAGE ? g_b1v : g_b0v;
            const float   barv = S.bar2[STAGE];
            const float   aI   = S.a[g];
            const float   ax = S.absv[g][2*i], ay = S.absv[g][2*i+1];
            const float4* cst = S.cst4 + STAGE*DR;

            // ---- score stage: scores + r2 cache + pos(e*nf) + compaction + reductions
            float nf1 = 0.f, sc1 = -1e30f;
            const int j1 = ltid;
            if (mi && j1 < NN) {
                nf1 = (S.neib[g][j1] && S.seqb[g][j1]) ? 1.f : 0.f;
                float bj = __ldcg(&gbv[j1]);
                float cx = ax - S.absv[g][2*j1], cy = ay - S.absv[g][2*j1+1];
                float scE = 0.f, scO = 0.f;
#pragma unroll
                for (int kp = 0; kp < 16; kp++) {
                    float4 c0 = cst[2*kp], c1 = cst[2*kp+1];
                    float r0 = fmaxf(fmaf(cx, c0.x, fmaf(cy, c0.y, c0.z)), 0.f);
                    float r1 = fmaxf(fmaf(cx, c1.x, fmaf(cy, c1.y, c1.z)), 0.f);
                    S.r2[g][kp*NN + j1] = make_float2(r0, r1);
                    scE += r0 * c0.w;
                    scO += r1 * c1.w;
                }
                float sc = scE + scO + aI + bj + barv;
                sc1 = (nf1 > 0.f) ? sc : -1e9f;
            }
            float e1 = __expf(sc1);     // masked -> 0
            if (j1 < NN) S.pos[g][j1] = e1 * nf1;   // UNNORMALIZED
            {   // compaction (needs only nf1; cnt was reset last stage under barrier)
                unsigned b1 = __ballot_sync(0xffffffffu, nf1 > 0.f);
                int base = 0;
                if (lane == 0 && b1) base = atomicAdd(&S.cnt[g], __popc(b1));
                base = __shfl_sync(0xffffffffu, base, 0);
                if (nf1 > 0.f)
                    S.actb[g][base + __popc(b1 & ((1u << lane) - 1u))] = (unsigned char)j1;
            }
            {   // merged reduction: sum(e), max(e*nf), sum(nf)
                float se = wsum(e1), mn = wmax(e1*nf1), sn = wsum(nf1);
                if (lane == 0) { S.rr[g][w8] = se; S.rr[g][8+w8] = mn; S.rr[g][16+w8] = sn; }
            }
            rbar(g);
            float ssum = 0.f, mpos = 0.f, neiRow = 0.f;
#pragma unroll
            for (int w = 0; w < 8; w++) {
                ssum += S.rr[g][w];
                mpos = fmaxf(mpos, S.rr[g][8+w]);
                neiRow += S.rr[g][16+w];
            }
            const float inv = (ssum > 0.f) ? 1.f/ssum : 0.f;
            const float maxposRow = mpos * inv;
            // ---- input prefetch for t+1 (stage1 only; absv/seqb/neib/xh dead now) ----
            if (STAGE == 1 && t + 1 < TT-1) {
                int t2 = t + 1;
                S.absv[g][ltid] = abs_[t2*2*NN + ltid];
                if (ltid < 2*NN - 256) S.absv[g][256 + ltid] = abs_[t2*2*NN + 256 + ltid];
                if (ltid < NN) {
                    S.seqb[g][ltid] = (unsigned char)(seq[t2*NN + ltid] > 0);
                    S.neib[g][ltid] =
                        (unsigned char)(nei[(size_t)t2*NN*NN + (size_t)i*NN + ltid] > 0);
                }
                if (ltid < DE) {
                    float n0 = norm[(t2*NN + i)*2 + 0];
                    float n1 = norm[(t2*NN + i)*2 + 1];
                    S.xh[g][ltid] = fmaxf(n0*w_in[ltid*2+0] + n1*w_in[ltid*2+1] + b_in[ltid], 0.f);
                }
            }
            // ---- gate + message loop: 2 neighbors/iter, 8 warps strided (balanced) ----
            const float Ai0 = S.A[g][lane]      + S.bg[STAGE*DH + lane];
            const float Ai1 = S.A[g][32 + lane] + S.bg[STAGE*DH + 32 + lane];
            const float4* wg4 = S.wg4 + STAGE*16*32;
            const float2* rS2 = S.r2[g];
            float msg0 = 0.f, msg1 = 0.f, v1p = 0.f;
            const int cnt = S.cnt[g];
            for (int a = 2*w8; a < cnt; a += 16) {
                int ja = S.actb[g][a];
                bool two = (a + 1) < cnt;
                int jb = two ? S.actb[g][a+1] : ja;
                float pa = S.pos[g][ja] * inv;
                float pb = two ? S.pos[g][jb] * inv : 0.f;
                float4 HA = __ldcg(&hBp[ja*32 + lane]);   // issued early,
                float4 HB = __ldcg(&hBp[jb*32 + lane]);   // consumed after k-loop
                float a0 = Ai0, a1 = Ai1, b0 = Ai0, b1 = Ai1;
#pragma unroll
                for (int kp = 0; kp < 16; kp++) {
                    float2 ra = rS2[kp*NN + ja];
                    float2 rb = rS2[kp*NN + jb];
                    float4 w4 = wg4[kp*32 + lane];
                    a0 += ra.x*w4.x + ra.y*w4.z;
                    a1 += ra.x*w4.y + ra.y*w4.w;
                    b0 += rb.x*w4.x + rb.y*w4.z;
                    b1 += rb.x*w4.y + rb.y*w4.w;
                }
                a0 += HA.z; a1 += HA.w;
                b0 += HB.z; b1 += HB.w;
                float ga0 = sigf(a0), ga1 = sigf(a1);
                float gb0 = sigf(b0), gb1 = sigf(b1);
                msg0 += pa*ga0*HA.x + pb*gb0*HB.x;
                msg1 += pa*ga1*HA.y + pb*gb1*HB.y;
                v1p  += ga0 + ga1;
                if (two) v1p += gb0 + gb1;   // don't count duplicated tail neighbor
            }
            S.msg2[g][w8][lane] = make_float2(msg0, msg1);
            if (STAGE == 0) {
                v1p = wsum(v1p);
                if (lane == 0) S.v1[g][w8] = v1p;
            }
            rbar(g);
            if (ltid < DH) {
                int h = ltid;
                float v = 0.f;
#pragma unroll
                for (int w = 0; w < 8; w++)
                    v += (h < 32) ? S.msg2[g][w][h].x : S.msg2[g][w][h-32].y;
                S.msgf[g][h] = v;
            }
            if (ltid == 128) S.cnt[g] = 0;   // safe: all gate-loop reads done (rbar above)
            rbar(g);
            // ---- merged cn GEMV + hn update (64 threads, 4 accumulators) ----
            if (ltid < DH) {
                int h = ltid;
                float cn = S.ctmp[g][h];
                float hn = S.hn[g][h];
                if (cnt) {
                    const float* wn = S.wnei + STAGE*4096;
                    float q0 = 0.f, q1 = 0.f, q2 = 0.f, q3 = 0.f;
#pragma unroll
                    for (int k = 0; k < 64; k += 4) {
                        q0 += S.msgf[g][k]   * wn[k*64 + h];
                        q1 += S.msgf[g][k+1] * wn[(k+1)*64 + h];
                        q2 += S.msgf[g][k+2] * wn[(k+2)*64 + h];
                        q3 += S.msgf[g][k+3] * wn[(k+3)*64 + h];
                    }
                    cn += (q0 + q1) + (q2 + q3);
                    hn = S.og[g][h]*tanhf(cn);
                }
                S.ctmp[g][h] = cn;
                S.hn[g][h] = hn;
                if (STAGE == 1 && mi) { S.h[g][h] = hn; S.c[g][h] = cn; }
            }
            rbar(g);
            if (STAGE == 0) {
                if (mi) {   // merged pre1 (full-k per warp) + stats
                    if (w8 == 0) {
                        const float2* wp = (const float2*)(g_wABT + 2*4096);
                        float sx = 0.f, sy = 0.f, tx = 0.f, ty = 0.f;
#pragma unroll
                        for (int k = 0; k < 64; k += 2) {
                            float h0 = S.hn[g][k], h1 = S.hn[g][k+1];
                            float2 w0 = wp[k*32 + lane], w1 = wp[(k+1)*32 + lane];
                            sx += h0*w0.x; sy += h0*w0.y;
                            tx += h1*w1.x; ty += h1*w1.y;
                        }
                        ((float2*)S.A[g])[lane] = make_float2(sx + tx, sy + ty);
                    } else if (w8 == 1) {
                        const float2* wp = (const float2*)(g_wABT + 3*4096);
                        float sx = 0.f, sy = 0.f, tx = 0.f, ty = 0.f;
#pragma unroll
                        for (int k = 0; k < 64; k += 2) {
                            float h0 = S.hn[g][k], h1 = S.hn[g][k+1];
                            float2 w0 = wp[k*32 + lane], w1 = wp[(k+1)*32 + lane];
                            sx += h0*w0.x; sy += h0*w0.y;
                            tx += h1*w1.x; ty += h1*w1.y;
                        }
                        float bx = sx + tx, by = sy + ty;
                        float e0 = __shfl_sync(0xffffffffu, bx, lane >> 1);
                        float e1b = __shfl_sync(0xffffffffu, by, lane >> 1);
                        float Bl = (lane & 1) ? e1b : e0;
                        float e2 = __shfl_sync(0xffffffffu, bx, 16 + (lane >> 1));
                        float e3 = __shfl_sync(0xffffffffu, by, 16 + (lane >> 1));
                        float Bh = (lane & 1) ? e3 : e2;
                        g_hB1p[i*32 + lane] = make_float4(S.hn[g][lane], S.hn[g][32 + lane], Bl, Bh);
                    } else if (w8 == 4) {
                        float pa = S.hn[g][lane]*S.war[128+lane] + S.hn[g][32+lane]*S.war[160+lane];
                        pa = wsum(pa);
                        if (lane == 0) S.a[g] = pa;
                    } else if (w8 == 5) {
                        float pb = S.hn[g][lane]*S.war[192+lane] + S.hn[g][32+lane]*S.war[224+lane];
                        pb = wsum(pb);
                        if (lane == 0) g_b1v[i] = pb;
                    } else if (w8 == 6 && lane == 0) {
                        float gateSum = 0.f;
#pragma unroll
                        for (int w = 0; w < 8; w++) gateSum += S.v1[g][w];
                        atomicAdd(&g_acc[0], gateSum);
                        atomicAdd(&g_acc[1], neiRow);
                        atomicAdd(&g_acc[2], maxposRow);
                        atomicAdd(&g_acc[3], neiRow > 0.f ? 1.f : 0.f);
                    }
                }
                gbar(target);
            } else {
                // outputs via 2 warp reductions
                if (w8 == 6) {
                    float o = S.hn[g][lane]*S.wout[lane] + S.hn[g][32+lane]*S.wout[32+lane];
                    o = wsum(o);
                    if (lane == 0) out[(t*NN + i)*2 + 0] = mi ? (o + S.bout[0]) : 0.f;
                } else if (w8 == 7) {
                    float o = S.hn[g][lane]*S.wout[64+lane] + S.hn[g][32+lane]*S.wout[96+lane];
                    o = wsum(o);
                    if (lane == 0) out[(t*NN + i)*2 + 1] = mi ? (o + S.bout[1]) : 0.f;
                }
            }
        }
        // no grid barrier between C and next A; groups are data-decoupled
    }

    // final writeback
    const int OFF = TT*NN*2;
    if (ltid < DH) {
        out[OFF + i*DH + ltid]         = S.h[g][ltid];
        out[OFF + NN*DH + i*DH + ltid] = S.c[g][ltid];
    }
    if (blockIdx.x == 0 && tid < 3) out[OFF + 2*NN*DH + tid] = g_v[tid] / (float)TT;
}

extern "C" void kernel_launch(void* const* d_in, const int* in_sizes, int n_in,
                              void* d_out, int out_size) {
    const float* abs_   = (const float*)d_in[0];
    const float* norm   = (const float*)d_in[1];
    const float* w_in   = (const float*)d_in[3];
    const float* b_in   = (const float*)d_in[4];
    const float* w_ih   = (const float*)d_in[5];
    const float* w_hh   = (const float*)d_in[6];
    const float* b_ih   = (const float*)d_in[7];
    const float* b_hh   = (const float*)d_in[8];
    const float* w_rel  = (const float*)d_in[9];
    const float* b_rel  = (const float*)d_in[10];
    const float* w_gate = (const float*)d_in[11];
    const float* b_gate = (const float*)d_in[12];
    const float* w_ar   = (const float*)d_in[13];
    const float* b_ar   = (const float*)d_in[14];
    const float* w_nei  = (const float*)d_in[15];
    const float* w_out  = (const float*)d_in[16];
    const float* b_out  = (const float*)d_in[17];
    const int*   seq    = (const int*)d_in[18];
    const int*   nei    = (const int*)d_in[19];
    float* out = (float*)d_out;

    cudaFuncSetAttribute(fused_kernel, cudaFuncAttributeMaxDynamicSharedMemorySize,
                         (int)sizeof(Smem));

    void* barptr = nullptr;
    cudaGetSymbolAddress(&barptr, g_bar);
    cudaMemsetAsync(barptr, 0, sizeof(unsigned), 0);

    fused_kernel<<<NB, NTH, sizeof(Smem)>>>(abs_, norm, w_in, b_in, w_ih, w_hh, b_ih, b_hh,
                                            w_rel, b_rel, w_gate, b_gate, w_ar, b_ar,
                                            w_nei, w_out, b_out, seq, nei, out);
}